// round 17
// baseline (speedup 1.0000x reference)
#include <cuda_runtime.h>

#define SZ 256
#define NCH 8
#define NPIX (SZ*SZ)
#define WPR 8         // words per row

// Per-channel occupancy bitmasks: 8 channels x 256 rows x 8 words = 64KB
__device__ unsigned int g_maskbits[NCH * SZ * WPR];

__global__ __launch_bounds__(1024) void build_masks_kernel(const int* __restrict__ lookup) {
    int tid = threadIdx.x;
    int y = blockIdx.x * 4 + (tid >> 8);
    int x = tid & 255;
    int v = lookup[y * SZ + x];
    int w = x >> 5;
    #pragma unroll
    for (int c = 0; c < NCH; ++c) {
        unsigned int mk = __ballot_sync(0xFFFFFFFFu, v == c + 1);
        if ((x & 31) == 0)
            g_maskbits[(c * SZ + y) * WPR + w] = mk;
    }
    cudaTriggerProgrammaticLaunchCompletion();
}

// Branchless top-4 insert (ascending 32-bit keys (d2<<16)|idx == top_k order:
// smallest d2, ties -> smallest flat idx). 7 IMNMX, self-filtering: keys with
// d2 > current 4th-best d2 are no-ops.
#define INS4(q0,q1,q2,q3,key)                                         \
    do { unsigned int _x = (key);                                     \
        unsigned int _y  = umin(_x, q3);                              \
        q3 = umax(q2, _y); unsigned int _y2 = umin(q2, _y);           \
        q2 = umax(q1, _y2); unsigned int _y1 = umin(q1, _y2);         \
        q1 = umax(q0, _y1); q0 = umin(q0, _y1);                       \
    } while (0)

// ------------------- Per-pixel path (R11, proven exact) -------------------
static __device__ __forceinline__ void process_pixel(
    const unsigned int* __restrict__ m, const unsigned char* __restrict__ isq,
    const float* __restrict__ sqlut, const float* __restrict__ img,
    float* __restrict__ out, int c, int y0, int x0)
{
    const int pix = (y0 << 8) + x0;

    if ((m[(y0 << 3) + (x0 >> 5)] >> (x0 & 31)) & 1u) {
        out[c * NPIX + pix] = __ldg(&img[pix]);
        return;
    }

    unsigned int k0 = ~0u, k1 = ~0u, k2 = ~0u, k3 = ~0u;
    bool done = false;

    // Fast path: interior, seed succeeds. If the 5x15 seed yields 4 neighbors,
    // B <= 53, continuation dy <= 7, u <= 6 -> in-bounds and exact.
    if (x0 >= 7 && x0 <= 248 && y0 >= 7 && y0 <= 248) {
        const int xlo = x0 - 7;
        const int wl  = xlo >> 5;
        const int sh  = xlo & 31;
        const unsigned int* row = &m[((y0 - 2) << 3) + wl];
        #pragma unroll
        for (int dy = -2; dy <= 2; ++dy, row += WPR) {
            unsigned int win = __funnelshift_r(row[0], row[1], sh) & 0x7FFFu;
            unsigned int base = ((unsigned int)(dy * dy) << 16)
                              + (unsigned int)(((y0 + dy) << 8) + xlo);
            while (win) {
                int b = __ffs(win) - 1;
                win &= win - 1;
                int dx = b - 7;
                INS4(k0,k1,k2,k3, base + (unsigned int)b + ((unsigned int)(dx * dx) << 16));
            }
        }
        if (k3 != ~0u) {
            for (int dy = 3; dy <= 7; ++dy) {
                unsigned int B = k3 >> 16;
                unsigned int dy2 = (unsigned int)(dy * dy);
                if (dy2 > B) break;
                int u = isq[B - dy2];
                int xl = x0 - u;
                int wl2 = xl >> 5, sh2 = xl & 31;
                unsigned int wmask = (2u << (2 * u)) - 1u;
                #pragma unroll
                for (int s = 0; s < 2; ++s) {
                    int yy = s ? y0 + dy : y0 - dy;
                    const unsigned int* r2 = &m[(yy << 3) + wl2];
                    unsigned int win = __funnelshift_r(r2[0], r2[1], sh2) & wmask;
                    unsigned int base = (dy2 << 16) + (unsigned int)((yy << 8) + xl);
                    while (win) {
                        int b = __ffs(win) - 1;
                        win &= win - 1;
                        int dx = b - u;
                        INS4(k0,k1,k2,k3, base + (unsigned int)b +
                              ((unsigned int)(dx * dx) << 16));
                    }
                }
            }
            done = true;
        }
    }

    unsigned int ridx[4], rd2[4];

    if (!done) {
        k0 = k1 = k2 = k3 = ~0u;   // discard partial fast-path seed (no dups)

        // General path: width-15 windows, exact iff final d2_4 < 256.
        auto scan_row = [&](int yy, int lo, int hi) {
            if ((unsigned)yy >= SZ) return;
            lo = lo < 0 ? 0 : lo;
            hi = hi > SZ - 1 ? SZ - 1 : hi;
            const unsigned int* row = &m[yy << 3];
            const int wl = lo >> 5;
            unsigned int win = __funnelshift_r(row[wl], row[wl + 1], lo);
            win &= 0xFFFFFFFFu >> (31 - (hi - lo));
            if (!win) return;
            const int dy = yy - y0;
            const unsigned int base =
                ((unsigned int)(dy * dy) << 16) + (unsigned int)((yy << 8) + lo);
            const int off = lo - x0;
            do {
                int b = __ffs(win) - 1;
                win &= win - 1;
                int dx = b + off;
                INS4(k0,k1,k2,k3, base + (unsigned int)b + ((unsigned int)(dx * dx) << 16));
            } while (win);
        };

        for (int dy = 0; dy < SZ; ++dy) {
            int u = 15;
            if (k3 != ~0u) {
                unsigned int B = k3 >> 16;
                unsigned int dy2 = (unsigned int)(dy * dy);
                if (dy2 > B) break;
                unsigned int rem = B - dy2;
                u = (rem >= 225u) ? 15 : (int)isq[rem];
            }
            scan_row(y0 - dy, x0 - u, x0 + u);
            if (dy > 0) scan_row(y0 + dy, x0 - u, x0 + u);
        }

        if (!(k3 != ~0u && (k3 >> 16) < 256u)) {
            // Essentially unreachable exact ring fallback
            unsigned long long b0 = ~0ULL, b1 = ~0ULL, b2 = ~0ULL, b3 = ~0ULL;
            int found = 0;
            auto visit = [&](int yy, int xx) {
                if ((unsigned)yy >= SZ || (unsigned)xx >= SZ) return;
                unsigned int word = m[(yy << 3) + (xx >> 5)];
                if ((word >> (xx & 31)) & 1u) {
                    int dy = yy - y0, dx = xx - x0;
                    unsigned int d2 = (unsigned int)(dy * dy + dx * dx);
                    unsigned long long key =
                        ((unsigned long long)d2 << 16) | (unsigned int)((yy << 8) + xx);
                    ++found;
                    if (key < b3) {
                        b3 = key;
                        if (b3 < b2) {
                            unsigned long long t = b2; b2 = b3; b3 = t;
                            if (b2 < b1) {
                                t = b1; b1 = b2; b2 = t;
                                if (b1 < b0) { t = b0; b0 = b1; b1 = t; }
                            }
                        }
                    }
                }
            };
            for (int r = 1; r < SZ; ++r) {
                if (found >= 4 && (unsigned int)(r * r) > (unsigned int)(b3 >> 16)) break;
                int yt = y0 - r, yb = y0 + r;
                for (int xx = x0 - r; xx <= x0 + r; ++xx) { visit(yt, xx); visit(yb, xx); }
                int xl = x0 - r, xr = x0 + r;
                for (int yy = y0 - r + 1; yy <= y0 + r - 1; ++yy) { visit(yy, xl); visit(yy, xr); }
            }
            unsigned long long keys[4] = { b0, b1, b2, b3 };
            #pragma unroll
            for (int i = 0; i < 4; ++i) {
                ridx[i] = (unsigned int)(keys[i] & 0xFFFFu);
                rd2[i]  = (unsigned int)(keys[i] >> 16);
            }
            goto output;
        }
    }

    ridx[0] = k0 & 0xFFFFu; rd2[0] = k0 >> 16;
    ridx[1] = k1 & 0xFFFFu; rd2[1] = k1 >> 16;
    ridx[2] = k2 & 0xFFFFu; rd2[2] = k2 >> 16;
    ridx[3] = k3 & 0xFFFFu; rd2[3] = k3 >> 16;

output:
    float num = 0.0f, den = 0.0f;
    #pragma unroll
    for (int i = 0; i < 4; ++i) {
        unsigned int d2 = rd2[i];
        float dist = (d2 < 256u) ? sqlut[d2]
                                 : sqrtf((float)d2) * (1.0f / 256.0f);
        num += __ldg(&img[ridx[i]]) * dist;
        den += dist;
    }
    out[c * NPIX + pix] = num / den;
}

// -------- Fused vertical-pair path: (yA,x0) and (yA+1,x0) share scans --------
static __device__ __forceinline__ void process_pair(
    const unsigned int* __restrict__ m, const unsigned char* __restrict__ isq,
    const float* __restrict__ sqlut, const float* __restrict__ img,
    float* __restrict__ out, int c, int yA, int x0)
{
    const int yB = yA + 1;
    const int pixA = (yA << 8) + x0;
    const int pixB = pixA + SZ;

    const bool filledA = (m[(yA << 3) + (x0 >> 5)] >> (x0 & 31)) & 1u;
    const bool filledB = (m[(yB << 3) + (x0 >> 5)] >> (x0 & 31)) & 1u;
    if (filledA && filledB) {
        out[c * NPIX + pixA] = __ldg(&img[pixA]);
        out[c * NPIX + pixB] = __ldg(&img[pixB]);
        return;
    }

    // Interior for BOTH pixels: x0 in [7,248], rows yA-7 .. yB+7 in bounds.
    if (!(x0 >= 7 && x0 <= 248 && yA >= 7 && yA <= 247)) {
        process_pixel(m, isq, sqlut, img, out, c, yA, x0);
        process_pixel(m, isq, sqlut, img, out, c, yB, x0);
        return;
    }

    unsigned int a0 = ~0u, a1 = ~0u, a2 = ~0u, a3 = ~0u;   // top-4 for A
    unsigned int b0 = ~0u, b1 = ~0u, b2 = ~0u, b3 = ~0u;   // top-4 for B

    // ---- Fused seed: rows yA-2 .. yA+3 (covers each pixel's |dy|<=2 5x15
    // seed plus one harmless extra row), shared 15-bit window per row. ----
    {
        const int xlo = x0 - 7;
        const int wl  = xlo >> 5;
        const int sh  = xlo & 31;
        const unsigned int* rp = &m[((yA - 2) << 3) + wl];
        #pragma unroll
        for (int i = 0; i < 6; ++i, rp += WPR) {
            const int dyA = i - 2;                 // -2..3
            const int dyB = i - 3;                 // -3..2
            unsigned int win = __funnelshift_r(rp[0], rp[1], sh) & 0x7FFFu;
            const int y = yA - 2 + i;
            unsigned int baseA = ((unsigned int)(dyA * dyA) << 16)
                               + (unsigned int)((y << 8) + xlo);
            unsigned int deltaB = ((unsigned int)(dyB * dyB)
                                 - (unsigned int)(dyA * dyA)) << 16;  // mod 2^32
            while (win) {
                int b = __ffs(win) - 1;
                win &= win - 1;
                int dx = b - 7;
                unsigned int key = baseA + (unsigned int)b
                                 + ((unsigned int)(dx * dx) << 16);
                INS4(a0,a1,a2,a3, key);
                INS4(b0,b1,b2,b3, key + deltaB);
            }
        }
    }

    if (a3 == ~0u || b3 == ~0u) {
        // Rare sparse seed: redo per pixel (fresh keys there; no duplicates).
        process_pixel(m, isq, sqlut, img, out, c, yA, x0);
        process_pixel(m, isq, sqlut, img, out, c, yB, x0);
        return;
    }

    // Seed found 4 for both: BA,BB <= 3^2+7^2 = 58 -> continuation distance
    // <= 7, half-width u <= 7, all rows in bounds. Inserts are self-filtering
    // (key with d2 > current 4th-best is a no-op), so both sets can take every
    // candidate in the union window; exactness per pixel needs only that all
    // cells with d2 <= its final d2_4 are visited, which the per-side
    // validity tests below guarantee (inclusive isq bounds keep ties).
    auto scan_pair = [&](int y, int u, unsigned int d2n, unsigned int d2f,
                         bool nearA) {
        const int xl = x0 - u;
        const unsigned int* r2 = &m[(y << 3) + (xl >> 5)];
        unsigned int win = __funnelshift_r(r2[0], r2[1], xl & 31)
                         & ((2u << (2 * u)) - 1u);
        unsigned int basen = (d2n << 16) + (unsigned int)((y << 8) + xl);
        unsigned int delta = (d2f - d2n) << 16;
        while (win) {
            int b = __ffs(win) - 1;
            win &= win - 1;
            int dx = b - u;
            unsigned int key = basen + (unsigned int)b
                             + ((unsigned int)(dx * dx) << 16);
            if (nearA) { INS4(a0,a1,a2,a3, key); INS4(b0,b1,b2,b3, key + delta); }
            else       { INS4(b0,b1,b2,b3, key); INS4(a0,a1,a2,a3, key + delta); }
        }
    };

    for (int dd = 3; dd <= 7; ++dd) {
        const unsigned int BA = a3 >> 16, BB = b3 >> 16;
        const unsigned int dd2 = (unsigned int)(dd * dd);
        const unsigned int de2 = (unsigned int)((dd + 1) * (dd + 1));
        // Row below A: distance dd from A, dd+1 from B
        bool vA = dd2 <= BA, vBf = de2 <= BB;
        // Row above B: distance dd from B, dd+1 from A
        bool vB = dd2 <= BB, vAf = de2 <= BA;
        if (!(vA | vBf | vB | vAf)) break;
        if (vA | vBf) {
            int u = max(vA ? (int)isq[BA - dd2] : 0,
                        vBf ? (int)isq[BB - de2] : 0);
            scan_pair(yA - dd, u, dd2, de2, true);
        }
        if (vB | vAf) {
            int u = max(vB ? (int)isq[BB - dd2] : 0,
                        vAf ? (int)isq[BA - de2] : 0);
            scan_pair(yB + dd, u, dd2, de2, false);
        }
    }

    // Epilogue: weighted by distance, in top_k order (all d2 <= 113 < 256).
    {
        float num = 0.0f, den = 0.0f;
        unsigned int ks[4] = { a0, a1, a2, a3 };
        #pragma unroll
        for (int i = 0; i < 4; ++i) {
            float dist = sqlut[ks[i] >> 16];
            num += __ldg(&img[ks[i] & 0xFFFFu]) * dist;
            den += dist;
        }
        out[c * NPIX + pixA] = filledA ? __ldg(&img[pixA]) : num / den;
    }
    {
        float num = 0.0f, den = 0.0f;
        unsigned int ks[4] = { b0, b1, b2, b3 };
        #pragma unroll
        for (int i = 0; i < 4; ++i) {
            float dist = sqlut[ks[i] >> 16];
            num += __ldg(&img[ks[i] & 0xFFFFu]) * dist;
            den += dist;
        }
        out[c * NPIX + pixB] = filledB ? __ldg(&img[pixB]) : num / den;
    }
}

__global__ __launch_bounds__(512, 3) void knn_fill_kernel(
    const float* __restrict__ img, float* __restrict__ out)
{
    const int c    = blockIdx.y;         // channel 0..7
    const int tid  = threadIdx.x;        // 0..511
    const int x0   = tid & 255;          // col
    const int pair = tid >> 8;           // which vertical pair

    // Channel bitmask (8KB) + pad words (masked out of windows).
    __shared__ __align__(16) unsigned int m[SZ * WPR + 4];
    __shared__ unsigned char isq[256];   // floor(sqrt(r)), r in [0,255]
    __shared__ float sqlut[256];         // sqrtf(r)/256 (bit-exact vs reference)

    // PDL prologue: LUTs are input-independent -> compute before the grid
    // dependency resolves, overlapping with build_masks_kernel.
    if (tid >= 256) {
        int r = tid - 256;
        int u = __float2int_rd(sqrtf((float)r));
        if ((u + 1) * (u + 1) <= r) ++u;
        if (u * u > r) --u;
        isq[r] = (unsigned char)u;
        sqlut[r] = sqrtf((float)r) * (1.0f / 256.0f);
    }

    cudaGridDependencySynchronize();     // build_masks results now visible

    if (tid < 256) {
        const uint4* src = (const uint4*)&g_maskbits[c * SZ * WPR];
        uint4* dst = (uint4*)m;
        dst[tid]       = src[tid];
        dst[tid + 256] = src[tid + 256];
    }
    __syncthreads();

    // Block covers 4 image rows: 2 vertical pairs x 256 columns.
    process_pair(m, isq, sqlut, img, out, c, blockIdx.x * 4 + pair * 2, x0);
}

extern "C" void kernel_launch(void* const* d_in, const int* in_sizes, int n_in,
                              void* d_out, int out_size) {
    const float* coded  = (const float*)d_in[0];   // [1,1,256,256]
    const int*   lookup = (const int*)d_in[1];     // [256,256]
    float* out = (float*)d_out;                    // [1,8,256,256]

    build_masks_kernel<<<SZ / 4, 1024>>>(lookup);

    cudaLaunchConfig_t cfg = {};
    cfg.gridDim  = dim3(SZ / 4, NCH);
    cfg.blockDim = dim3(512);
    cfg.stream   = 0;
    cudaLaunchAttribute attr[1];
    attr[0].id = cudaLaunchAttributeProgrammaticStreamSerialization;
    attr[0].val.programmaticStreamSerializationAllowed = 1;
    cfg.attrs = attr;
    cfg.numAttrs = 1;
    cudaLaunchKernelEx(&cfg, knn_fill_kernel, coded, out);
}